// round 15
// baseline (speedup 1.0000x reference)
#include <cuda_runtime.h>
#include <cuda_bf16.h>
#include <math.h>
#include <string.h>

// support [25,2560] f32, query [4096,2560] f32 -> out [4096,5] f32
#define D       2560
#define NS      25
#define NSB     26              // 25 supports + 1 ones-row (gives qsum)
#define NPAD    32
#define NWAY    5
#define KSHOT   5
#define EPSV    1e-6f

#define NSPLIT  8
#define DQ      320             // K per CTA (f32)
#define MROWS   128             // query rows per CTA
#define NRB     32              // NQ / MROWS
#define THREADS 256
#define BSTRIDE 336             // bf16/row (R14-proven conflict-free for LDS.64)

#define KSUB    64              // f32 cols per ring stage
#define NSTG    5               // DQ / KSUB
#define RING    2
#define QSTR    80              // f32 row stride in ring; 80 mod 32 = 16 -> LDS.128 conflict-free
#define STAGEF  (MROWS * QSTR)  // 10240 f32
#define DSMEM   (RING * STAGEF * 4)   // 81920 bytes

typedef unsigned long long u64;

__device__ float g_dot[NSPLIT][NRB][NSB][MROWS];
__device__ float g_qn [NSPLIT][NRB][MROWS];
__device__ float g_sn [NSPLIT][NS];
__device__ int   g_ctr[NRB];    // zero-init; self-resetting per launch

__device__ __forceinline__ u64 ffma2(u64 a, u64 b, u64 c) {
    u64 d;
    asm("fma.rn.f32x2 %0, %1, %2, %3;" : "=l"(d) : "l"(a), "l"(b), "l"(c));
    return d;
}
__device__ __forceinline__ float f2_sum(u64 v) {
    return __uint_as_float((unsigned)(v & 0xffffffffull)) +
           __uint_as_float((unsigned)(v >> 32));
}
__device__ __forceinline__ unsigned cvt_bf2(float x, float y) {
    __nv_bfloat162 p = __floats2bfloat162_rn(x, y);
    unsigned r; memcpy(&r, &p, 4); return r;
}
__device__ __forceinline__ void mma16816(float c[4],
                                         unsigned a0, unsigned a1,
                                         unsigned a2, unsigned a3,
                                         unsigned b0, unsigned b1) {
    asm volatile(
        "mma.sync.aligned.m16n8k16.row.col.f32.bf16.bf16.f32 "
        "{%0,%1,%2,%3}, {%4,%5,%6,%7}, {%8,%9}, {%0,%1,%2,%3};"
        : "+f"(c[0]), "+f"(c[1]), "+f"(c[2]), "+f"(c[3])
        : "r"(a0), "r"(a1), "r"(a2), "r"(a3), "r"(b0), "r"(b1));
}

// ---------------------------------------------------------------------------
// R14 champion fragment math (phys-k mapping: slot tig carries physical cols
// 4t..4t+3 on BOTH A and B sides) with the A-path moved from a register
// prefetch pipeline (which hit the 128-reg cap and exposed DRAM latency)
// to a 2-slot x 40KB cp.async ring:
//   stage = 128 rows x 64 f32 (256B contiguous per row per warp-instr)
//   QSTR=80 -> row-parity banking, LDS.128 fragments conflict-free
// CTA = (row block rb: 128 rows, K-eighth qd), 8 warps x 16 rows, occ 2.
// B (support bf16) staged once; row 25 = ones -> qsum free. fp32 qn from the
// staged raw values. Last-CTA-per-rowblock fused finisher (R7-proven).
// ---------------------------------------------------------------------------
__global__ __launch_bounds__(THREADS, 2)
void pd_mma(const float* __restrict__ support,
            const float* __restrict__ query,
            float* __restrict__ out) {
    extern __shared__ float Qs[];                // [RING][MROWS][QSTR]
    __shared__ __align__(16) __nv_bfloat16 Bs[NPAD][BSTRIDE];
    __shared__ float s_red[NS][8][2];
    __shared__ float s_sn[NS];
    __shared__ int   s_flag;

    const int tid  = threadIdx.x;
    const int warp = tid >> 5;
    const int ln   = tid & 31;
    const int gid  = ln >> 2;
    const int tig  = ln & 3;
    const int rb   = blockIdx.x;
    const int qd   = blockIdx.y;
    const int dstart = qd * DQ;

    const float* qbase = query + (size_t)rb * MROWS * D + dstart;

    // ---- cp.async stage issue: warp-instr = 2 rows x 256B contiguous ----
    const int srow = warp * 16 + (ln >> 4);      // this thread's base row
    const int sseg = ln & 15;                    // 16B segment within 256B
    auto issue_stage = [&](int st) {
        if (st < NSTG) {
            float* buf = Qs + (st & (RING - 1)) * STAGEF;
            const int kb = st * KSUB;
            #pragma unroll
            for (int j = 0; j < 8; ++j) {
                const int row = srow + 2 * j;
                const float* src = qbase + (size_t)row * D + kb + sseg * 4;
                const unsigned dst = (unsigned)__cvta_generic_to_shared(
                    buf + row * QSTR + sseg * 4);
                asm volatile("cp.async.cg.shared.global [%0], [%1], 16;"
                             :: "r"(dst), "l"(src));
            }
        }
        asm volatile("cp.async.commit_group;");
    };
    issue_stage(0); issue_stage(1);

    // ---- ones row (25) and zero pad rows (26..31) ----
    for (int i = tid; i < (NPAD - NS) * BSTRIDE; i += THREADS) {
        const int r = NS + i / BSTRIDE;
        const int c = i % BSTRIDE;
        Bs[r][c] = __float2bfloat16(r == NS ? 1.f : 0.f);
    }

    // ---- stage B: 25x320 f32 -> bf16 (rounded), plus ssq/ssm partials ----
    if (tid < NS * 8) {
        const int n  = tid >> 3;
        const int kc = tid & 7;                    // 40-col strip
        const float* src = support + (size_t)n * D + dstart + kc * 40;
        float ssq = 0.f, ssm = 0.f;
        #pragma unroll
        for (int j = 0; j < 10; ++j) {
            const float4 v = *reinterpret_cast<const float4*>(src + j * 4);
            const __nv_bfloat162 p0 = __floats2bfloat162_rn(v.x, v.y);
            const __nv_bfloat162 p1 = __floats2bfloat162_rn(v.z, v.w);
            const float r0 = __bfloat162float(p0.x), r1 = __bfloat162float(p0.y);
            const float r2 = __bfloat162float(p1.x), r3 = __bfloat162float(p1.y);
            ssq = fmaf(r0, r0, ssq); ssq = fmaf(r1, r1, ssq);
            ssq = fmaf(r2, r2, ssq); ssq = fmaf(r3, r3, ssq);
            ssm += (r0 + r1) + (r2 + r3);
            u64 u; memcpy(&u, &p0, 4); memcpy(((char*)&u) + 4, &p1, 4);
            *reinterpret_cast<u64*>(&Bs[n][kc * 40 + j * 4]) = u;
        }
        s_red[n][kc][0] = ssq;
        s_red[n][kc][1] = ssm;
    }
    __syncthreads();
    if (tid < NS) {
        float a = 0.f, b = 0.f;
        #pragma unroll
        for (int o = 0; o < 8; ++o) { a += s_red[tid][o][0]; b += s_red[tid][o][1]; }
        g_sn[qd][tid] = a + 2.f * EPSV * b;   // ||s~||^2 + 2 eps sum(s~) (eighth)
    }

    // ---- mainloop: 5 stages x 4 chunks of 16 cols ----
    const int lrow = warp * 16 + gid;
    float c[4][4];
    #pragma unroll
    for (int nt = 0; nt < 4; ++nt)
        #pragma unroll
        for (int i = 0; i < 4; ++i) c[nt][i] = 0.f;
    u64 qn0 = 0ull, qn1 = 0ull;
    const int aoff = lrow * QSTR + tig * 4;

    for (int st = 0; st < NSTG; ++st) {
        asm volatile("cp.async.wait_group 1;");   // stage st fully arrived
        __syncthreads();
        const float* Arow = Qs + (st & (RING - 1)) * STAGEF + aoff;
        #pragma unroll
        for (int ch = 0; ch < 4; ++ch) {
            const float4 vA = *reinterpret_cast<const float4*>(Arow + ch * 16);
            const float4 vB = *reinterpret_cast<const float4*>(
                Arow + 8 * QSTR + ch * 16);
            {   // fp32 qn from the raw values (permutation-invariant)
                u64 lo, hi;
                memcpy(&lo, &vA.x, 8); memcpy(&hi, &vA.z, 8);
                qn0 = ffma2(lo, lo, qn0); qn0 = ffma2(hi, hi, qn0);
                memcpy(&lo, &vB.x, 8); memcpy(&hi, &vB.z, 8);
                qn1 = ffma2(lo, lo, qn1); qn1 = ffma2(hi, hi, qn1);
            }
            const unsigned ra0 = cvt_bf2(vA.x, vA.y);   // phys 4t,4t+1
            const unsigned ra2 = cvt_bf2(vA.z, vA.w);   // phys 4t+2,4t+3
            const unsigned ra1 = cvt_bf2(vB.x, vB.y);
            const unsigned ra3 = cvt_bf2(vB.z, vB.w);
            const int k0 = (st * 4 + ch) * 16 + tig * 4;
            #pragma unroll
            for (int nt = 0; nt < 4; ++nt) {
                const u64 bv =
                    *reinterpret_cast<const u64*>(&Bs[nt * 8 + gid][k0]);
                mma16816(c[nt], ra0, ra1, ra2, ra3,
                         (unsigned)(bv & 0xffffffffull), (unsigned)(bv >> 32));
            }
        }
        __syncthreads();          // slot fully consumed before refill
        issue_stage(st + RING);   // empty commits past the end keep counts sane
    }

    // ---- qn: reduce over the 4 quad lanes (same row) ----
    float q0 = f2_sum(qn0), q1 = f2_sum(qn1);
    q0 += __shfl_xor_sync(0xffffffffu, q0, 1);
    q0 += __shfl_xor_sync(0xffffffffu, q0, 2);
    q1 += __shfl_xor_sync(0xffffffffu, q1, 1);
    q1 += __shfl_xor_sync(0xffffffffu, q1, 2);
    if (tig == 0) {
        g_qn[qd][rb][lrow]     = q0;
        g_qn[qd][rb][lrow + 8] = q1;
    }

    // ---- publish dot partials (disjoint (row,col) per lane) ----
    #pragma unroll
    for (int nt = 0; nt < 4; ++nt) {
        const int s = nt * 8 + tig * 2;
        if (s < NSB) {
            g_dot[qd][rb][s][lrow]     = c[nt][0];
            g_dot[qd][rb][s][lrow + 8] = c[nt][2];
        }
        if (s + 1 < NSB) {
            g_dot[qd][rb][s + 1][lrow]     = c[nt][1];
            g_dot[qd][rb][s + 1][lrow + 8] = c[nt][3];
        }
    }

    __threadfence();
    __syncthreads();
    if (tid == 0) s_flag = atomicAdd(&g_ctr[rb], 1);
    __syncthreads();

    // ---- last CTA of this row block finishes ----
    if (s_flag == NSPLIT - 1) {
        if (tid < NS) {
            float a = 0.f;
            #pragma unroll
            for (int q = 0; q < NSPLIT; ++q) a += g_sn[q][tid];
            s_sn[tid] = a;
        }
        __syncthreads();
        if (tid < MROWS) {
            const int r = tid;
            float dt[NS];
            #pragma unroll
            for (int s = 0; s < NS; ++s) dt[s] = 0.f;
            float qnT = 0.f, qsT = 0.f;
            #pragma unroll
            for (int q = 0; q < NSPLIT; ++q) {
                #pragma unroll
                for (int s = 0; s < NS; ++s) dt[s] += g_dot[q][rb][s][r];
                qsT += g_dot[q][rb][25][r];     // ones-row dot = sum(q~)
                qnT += g_qn[q][rb][r];
            }
            // d2 = qn + (ssq + 2 eps ssm) + D eps^2 - 2 dot - 2 eps qsum
            const float base = qnT - 2.f * EPSV * qsT + (float)D * (EPSV * EPSV);
            #pragma unroll
            for (int w = 0; w < NWAY; ++w) {
                float sum = 0.f;
                #pragma unroll
                for (int k = 0; k < KSHOT; ++k) {
                    const int s = w * KSHOT + k;
                    const float d2 = base + s_sn[s] - 2.f * dt[s];
                    sum += sqrtf(fmaxf(d2, 0.f));
                }
                out[(size_t)(rb * MROWS + r) * NWAY + w] = -sum;
            }
        }
        if (tid == 0) g_ctr[rb] = 0;   // reset for next replay
    }
}

// ---------------------------------------------------------------------------
extern "C" void kernel_launch(void* const* d_in, const int* in_sizes, int n_in,
                              void* d_out, int out_size) {
    const float* support = (const float*)d_in[0];
    const float* query   = (const float*)d_in[1];
    if (n_in >= 2 && in_sizes[0] > in_sizes[1]) {
        const float* t = support; support = query; query = t;
    }
    float* out = (float*)d_out;

    cudaFuncSetAttribute(pd_mma, cudaFuncAttributeMaxDynamicSharedMemorySize,
                         DSMEM);
    pd_mma<<<dim3(NRB, NSPLIT), THREADS, DSMEM>>>(support, query, out);
}

// round 16
// speedup vs baseline: 1.2405x; 1.2405x over previous
#include <cuda_runtime.h>
#include <cuda_bf16.h>
#include <math.h>
#include <string.h>

// support [25,2560] f32, query [4096,2560] f32 -> out [4096,5] f32
#define D       2560
#define NS      25
#define NSB     26              // 25 supports + 1 ones-row (gives qsum)
#define NPAD    32
#define NWAY    5
#define KSHOT   5
#define EPSV    1e-6f

#define NSPLIT  8
#define DQ      320             // K per CTA
#define NCHUNK  20              // DQ / 16
#define MROWS   128             // query rows per CTA
#define NRB     32              // NQ / MROWS
#define THREADS 256
#define BSTRIDE 336             // bf16/row: conflict-free per LDS.64 half-warp phase
#define PF      4               // A prefetch depth (chunks)

typedef unsigned long long u64;

__device__ float g_dot[NSPLIT][NRB][NSB][MROWS];
__device__ float g_qn [NSPLIT][NRB][MROWS];
__device__ float g_sn [NSPLIT][NS];
__device__ int   g_ctr[NRB];    // zero-init; self-resetting per launch

__device__ __forceinline__ u64 ffma2(u64 a, u64 b, u64 c) {
    u64 d;
    asm("fma.rn.f32x2 %0, %1, %2, %3;" : "=l"(d) : "l"(a), "l"(b), "l"(c));
    return d;
}
__device__ __forceinline__ float f2_sum(u64 v) {
    return __uint_as_float((unsigned)(v & 0xffffffffull)) +
           __uint_as_float((unsigned)(v >> 32));
}
__device__ __forceinline__ unsigned cvt_bf2(float x, float y) {
    __nv_bfloat162 p = __floats2bfloat162_rn(x, y);
    unsigned r; memcpy(&r, &p, 4); return r;
}
// non-coherent LDG.128 with 256B L2 prefetch (pulls the sibling half-line
// that the NEXT chunk of this quad will consume)
__device__ __forceinline__ float4 ldg_nc_pf(const float* p) {
    float4 v;
    asm("ld.global.nc.L2::256B.v4.f32 {%0,%1,%2,%3}, [%4];"
        : "=f"(v.x), "=f"(v.y), "=f"(v.z), "=f"(v.w) : "l"(p));
    return v;
}
__device__ __forceinline__ float4 ldg_nc(const float* p) {
    float4 v;
    asm("ld.global.nc.v4.f32 {%0,%1,%2,%3}, [%4];"
        : "=f"(v.x), "=f"(v.y), "=f"(v.z), "=f"(v.w) : "l"(p));
    return v;
}
__device__ __forceinline__ void mma16816(float c[4],
                                         unsigned a0, unsigned a1,
                                         unsigned a2, unsigned a3,
                                         unsigned b0, unsigned b1) {
    asm volatile(
        "mma.sync.aligned.m16n8k16.row.col.f32.bf16.bf16.f32 "
        "{%0,%1,%2,%3}, {%4,%5,%6,%7}, {%8,%9}, {%0,%1,%2,%3};"
        : "+f"(c[0]), "+f"(c[1]), "+f"(c[2]), "+f"(c[3])
        : "r"(a0), "r"(a1), "r"(a2), "r"(a3), "r"(b0), "r"(b1));
}

// ---------------------------------------------------------------------------
// R14 champion (17.15us) + latency micro-opts:
//   - A loads: ld.global.nc.L2::256B (prefetch sibling half-line)
//   - PF prologue hoisted ABOVE B staging (DRAM latency hidden behind it)
//   - B staging via nc loads (support is L2-resident after first CTAs)
// Fragment math unchanged (phys-k mapping: slot tig carries physical cols
// 4t..4t+3 on BOTH A and B sides; A = one LDG.128/row/chunk, B = one
// LDS.64/n-tile). CTA = (row block rb: 128 rows, K-eighth qd), 8 warps x
// 16 rows, occ 2. Row 25 of B = ones -> qsum free; fp32 qn from raw loads;
// last-CTA-per-rowblock fused finisher.
// ---------------------------------------------------------------------------
__global__ __launch_bounds__(THREADS, 2)
void pd_mma(const float* __restrict__ support,
            const float* __restrict__ query,
            float* __restrict__ out) {
    __shared__ __align__(16) __nv_bfloat16 Bs[NPAD][BSTRIDE];
    __shared__ float s_red[NS][8][2];
    __shared__ float s_sn[NS];
    __shared__ int   s_flag;

    const int tid  = threadIdx.x;
    const int warp = tid >> 5;
    const int ln   = tid & 31;
    const int gid  = ln >> 2;
    const int tig  = ln & 3;
    const int rb   = blockIdx.x;
    const int qd   = blockIdx.y;
    const int dstart = qd * DQ;

    // ---- A prefetch pipeline: issue FIRST so DRAM latency hides behind
    //      the B staging work below ----
    const int lrow = warp * 16 + gid;
    const float* qa = query + (size_t)(rb * MROWS + lrow) * D + dstart + tig * 4;
    const float* qb = qa + (size_t)8 * D;

    float4 pa[PF][2];
    #pragma unroll
    for (int p = 0; p < PF; ++p) {
        pa[p][0] = ldg_nc_pf(qa + p * 16);
        pa[p][1] = ldg_nc_pf(qb + p * 16);
    }

    // ---- ones row (25) and zero pad rows (26..31) ----
    for (int i = tid; i < (NPAD - NS) * BSTRIDE; i += THREADS) {
        const int r = NS + i / BSTRIDE;
        const int c = i % BSTRIDE;
        Bs[r][c] = __float2bfloat16(r == NS ? 1.f : 0.f);
    }

    // ---- stage B: 25x320 f32 -> bf16 (rounded), plus ssq/ssm partials ----
    if (tid < NS * 8) {
        const int n  = tid >> 3;
        const int kc = tid & 7;                    // 40-col strip
        const float* src = support + (size_t)n * D + dstart + kc * 40;
        float ssq = 0.f, ssm = 0.f;
        #pragma unroll
        for (int j = 0; j < 10; ++j) {
            const float4 v = ldg_nc(src + j * 4);
            const __nv_bfloat162 p0 = __floats2bfloat162_rn(v.x, v.y);
            const __nv_bfloat162 p1 = __floats2bfloat162_rn(v.z, v.w);
            const float r0 = __bfloat162float(p0.x), r1 = __bfloat162float(p0.y);
            const float r2 = __bfloat162float(p1.x), r3 = __bfloat162float(p1.y);
            ssq = fmaf(r0, r0, ssq); ssq = fmaf(r1, r1, ssq);
            ssq = fmaf(r2, r2, ssq); ssq = fmaf(r3, r3, ssq);
            ssm += (r0 + r1) + (r2 + r3);
            u64 u; memcpy(&u, &p0, 4); memcpy(((char*)&u) + 4, &p1, 4);
            *reinterpret_cast<u64*>(&Bs[n][kc * 40 + j * 4]) = u;
        }
        s_red[n][kc][0] = ssq;
        s_red[n][kc][1] = ssm;
    }
    __syncthreads();
    if (tid < NS) {
        float a = 0.f, b = 0.f;
        #pragma unroll
        for (int o = 0; o < 8; ++o) { a += s_red[tid][o][0]; b += s_red[tid][o][1]; }
        g_sn[qd][tid] = a + 2.f * EPSV * b;   // ||s~||^2 + 2 eps sum(s~) (eighth)
    }

    // ---- mainloop: 20 k-chunks of 16, 4 n-tiles, LDG.128 A, PF=4 ----
    float c[4][4];
    #pragma unroll
    for (int nt = 0; nt < 4; ++nt)
        #pragma unroll
        for (int i = 0; i < 4; ++i) c[nt][i] = 0.f;
    u64 qn0 = 0ull, qn1 = 0ull;

    #pragma unroll
    for (int ch = 0; ch < NCHUNK; ++ch) {
        const int slot = ch & (PF - 1);
        const float4 vA = pa[slot][0];
        const float4 vB = pa[slot][1];
        if (ch + PF < NCHUNK) {
            pa[slot][0] = ldg_nc_pf(qa + (ch + PF) * 16);
            pa[slot][1] = ldg_nc_pf(qb + (ch + PF) * 16);
        }
        {   // fp32 qn from the raw values (permutation-invariant)
            u64 lo, hi;
            memcpy(&lo, &vA.x, 8); memcpy(&hi, &vA.z, 8);
            qn0 = ffma2(lo, lo, qn0); qn0 = ffma2(hi, hi, qn0);
            memcpy(&lo, &vB.x, 8); memcpy(&hi, &vB.z, 8);
            qn1 = ffma2(lo, lo, qn1); qn1 = ffma2(hi, hi, qn1);
        }
        const unsigned ra0 = cvt_bf2(vA.x, vA.y);   // phys 4t,4t+1
        const unsigned ra2 = cvt_bf2(vA.z, vA.w);   // phys 4t+2,4t+3
        const unsigned ra1 = cvt_bf2(vB.x, vB.y);
        const unsigned ra3 = cvt_bf2(vB.z, vB.w);
        const int k0 = ch * 16 + tig * 4;
        #pragma unroll
        for (int nt = 0; nt < 4; ++nt) {
            const u64 bv = *reinterpret_cast<const u64*>(&Bs[nt * 8 + gid][k0]);
            mma16816(c[nt], ra0, ra1, ra2, ra3,
                     (unsigned)(bv & 0xffffffffull), (unsigned)(bv >> 32));
        }
    }

    // ---- qn: reduce over the 4 quad lanes (same row) ----
    float q0 = f2_sum(qn0), q1 = f2_sum(qn1);
    q0 += __shfl_xor_sync(0xffffffffu, q0, 1);
    q0 += __shfl_xor_sync(0xffffffffu, q0, 2);
    q1 += __shfl_xor_sync(0xffffffffu, q1, 1);
    q1 += __shfl_xor_sync(0xffffffffu, q1, 2);
    if (tig == 0) {
        g_qn[qd][rb][lrow]     = q0;
        g_qn[qd][rb][lrow + 8] = q1;
    }

    // ---- publish dot partials (disjoint (row,col) per lane) ----
    #pragma unroll
    for (int nt = 0; nt < 4; ++nt) {
        const int s = nt * 8 + tig * 2;
        if (s < NSB) {
            g_dot[qd][rb][s][lrow]     = c[nt][0];
            g_dot[qd][rb][s][lrow + 8] = c[nt][2];
        }
        if (s + 1 < NSB) {
            g_dot[qd][rb][s + 1][lrow]     = c[nt][1];
            g_dot[qd][rb][s + 1][lrow + 8] = c[nt][3];
        }
    }

    __threadfence();
    __syncthreads();
    if (tid == 0) s_flag = atomicAdd(&g_ctr[rb], 1);
    __syncthreads();

    // ---- last CTA of this row block finishes ----
    if (s_flag == NSPLIT - 1) {
        if (tid < NS) {
            float a = 0.f;
            #pragma unroll
            for (int q = 0; q < NSPLIT; ++q) a += g_sn[q][tid];
            s_sn[tid] = a;
        }
        __syncthreads();
        if (tid < MROWS) {
            const int r = tid;
            float dt[NS];
            #pragma unroll
            for (int s = 0; s < NS; ++s) dt[s] = 0.f;
            float qnT = 0.f, qsT = 0.f;
            #pragma unroll
            for (int q = 0; q < NSPLIT; ++q) {
                #pragma unroll
                for (int s = 0; s < NS; ++s) dt[s] += g_dot[q][rb][s][r];
                qsT += g_dot[q][rb][25][r];     // ones-row dot = sum(q~)
                qnT += g_qn[q][rb][r];
            }
            // d2 = qn + (ssq + 2 eps ssm) + D eps^2 - 2 dot - 2 eps qsum
            const float base = qnT - 2.f * EPSV * qsT + (float)D * (EPSV * EPSV);
            #pragma unroll
            for (int w = 0; w < NWAY; ++w) {
                float sum = 0.f;
                #pragma unroll
                for (int k = 0; k < KSHOT; ++k) {
                    const int s = w * KSHOT + k;
                    const float d2 = base + s_sn[s] - 2.f * dt[s];
                    sum += sqrtf(fmaxf(d2, 0.f));
                }
                out[(size_t)(rb * MROWS + r) * NWAY + w] = -sum;
            }
        }
        if (tid == 0) g_ctr[rb] = 0;   // reset for next replay
    }
}

// ---------------------------------------------------------------------------
extern "C" void kernel_launch(void* const* d_in, const int* in_sizes, int n_in,
                              void* d_out, int out_size) {
    const float* support = (const float*)d_in[0];
    const float* query   = (const float*)d_in[1];
    if (n_in >= 2 && in_sizes[0] > in_sizes[1]) {
        const float* t = support; support = query; query = t;
    }
    float* out = (float*)d_out;

    pd_mma<<<dim3(NRB, NSPLIT), THREADS>>>(support, query, out);
}